// round 13
// baseline (speedup 1.0000x reference)
#include <cuda_runtime.h>
#include <cuda_bf16.h>

#define T_TOKENS 16384
#define H_DIM    2880
#define E_EXP    32
#define TOPK     4
#define BM       64
#define NWARP    12
#define KPW      (H_DIM / NWARP)    // 240 per warp
#define NST      (KPW / 16)         // 15 stages of k16 per warp
#define NTHREADS (NWARP * 32)       // 384
#define XROW     768                // 48 chunks of 16B (12 warps x 4)
#define WROW     384                // 24 chunks of 16B (12 warps x 2)
#define WPLANE   (E_EXP * WROW)     // 12288

// W bf16 hi/lo planes, k-INTERLEAVED within each 16-group so one LDS.64 = (b0,b1) frag:
// pos(k) within 16: {0,1,8,9, 2,3,10,11, 4,5,12,13, 6,7,14,15}
__device__ __nv_bfloat16 g_wh[E_EXP * H_DIM];
__device__ __nv_bfloat16 g_wl[E_EXP * H_DIM];

__global__ __launch_bounds__(256)
void convert_w(const float* __restrict__ w)
{
    int i = blockIdx.x * 256 + threadIdx.x;
    if (i < E_EXP * H_DIM) {
        int k   = i % H_DIM;
        int kb  = k & ~15;
        int k16 = k & 15;
        int pos = ((k16 & 7) >> 1) * 4 + ((k16 >> 3) << 1) + (k16 & 1);
        int j   = i - k + kb + pos;
        float v = w[i];
        __nv_bfloat16 h = __float2bfloat16_rn(v);
        g_wh[j] = h;
        g_wl[j] = __float2bfloat16_rn(v - __bfloat162float(h));
    }
}

__device__ __forceinline__ unsigned smem_u32(const void* p) {
    return (unsigned)__cvta_generic_to_shared(p);
}
__device__ __forceinline__ void cp16(unsigned dst, const void* src) {
    asm volatile("cp.async.cg.shared.global [%0], [%1], 16;" :: "r"(dst), "l"(src));
}
__device__ __forceinline__ void cp_commit() {
    asm volatile("cp.async.commit_group;");
}
template <int N>
__device__ __forceinline__ void cp_wait() {
    asm volatile("cp.async.wait_group %0;" :: "n"(N));
}
__device__ __forceinline__ void cvt_hl(float2 f, unsigned& h, unsigned& l)
{
    asm("cvt.rn.bf16x2.f32 %0, %1, %2;" : "=r"(h) : "f"(f.y), "f"(f.x));
    float h0 = __uint_as_float(h << 16);
    float h1 = __uint_as_float(h & 0xffff0000u);
    asm("cvt.rn.bf16x2.f32 %0, %1, %2;" : "=r"(l) : "f"(f.y - h1), "f"(f.x - h0));
}
__device__ __forceinline__ void hmma(float* d, const unsigned* a, unsigned b0, unsigned b1)
{
    asm volatile(
        "mma.sync.aligned.m16n8k16.row.col.f32.bf16.bf16.f32 "
        "{%0,%1,%2,%3}, {%4,%5,%6,%7}, {%8,%9}, {%0,%1,%2,%3};"
        : "+f"(d[0]), "+f"(d[1]), "+f"(d[2]), "+f"(d[3])
        : "r"(a[0]), "r"(a[1]), "r"(a[2]), "r"(a[3]), "r"(b0), "r"(b1));
}

__global__ __launch_bounds__(NTHREADS, 1)
void gate_mma(const float* __restrict__ x,
              const float* __restrict__ bias,
              float* __restrict__ out)
{
    // Shared buffers; warp-private chunk regions via bijective XOR swizzle.
    __shared__ __align__(16) char xsm[3][BM * XROW];        // 144 KB (x: [tok][48 chunks])
    __shared__ __align__(16) char wsm[3][2 * E_EXP * WROW]; // 72 KB  (w: [pl][e][24 chunks])

    const int tid  = threadIdx.x;
    const int warp = tid >> 5;
    const int lane = tid & 31;
    const int gid  = lane >> 2;       // 0..7
    const int tig  = lane & 3;        // 0..3
    const int t0   = blockIdx.x * BM;
    const int kb   = warp * KPW;      // this warp's K base

    // ---- warp-private staging maps ----
    // x: 256 chunks/stage/warp (64 tok x 4): id = lane + 32*i (i<8): tok=id>>2, kc=id&3
    const float* xsrc[8];
    int xdo[8];
    #pragma unroll
    for (int i = 0; i < 8; ++i) {
        int id  = lane + 32 * i;
        int tok = id >> 2, kc = id & 3;
        xsrc[i] = x + (size_t)(t0 + tok) * H_DIM + kb + kc * 4;
        xdo[i]  = tok * XROW + (((4 * warp + kc) ^ (tok & 7)) << 4);
    }
    // w: 128 chunks/stage/warp (2 pl x 32 e x 2 halves): id = lane + 32*i (i<4)
    const __nv_bfloat16* wsrc[4];
    int wdo[4];
    #pragma unroll
    for (int i = 0; i < 4; ++i) {
        int id = lane + 32 * i;
        int pl = id >> 6, e = (id >> 1) & 31, h = id & 1;
        wsrc[i] = (pl ? g_wl : g_wh) + (size_t)e * H_DIM + kb + h * 8;
        wdo[i]  = pl * WPLANE + e * WROW + (((2 * warp + h) ^ (e & 7)) << 4);
    }

    auto stage = [&](int s, int b) {
        const size_t ko = (size_t)s * 16;
        #pragma unroll
        for (int i = 0; i < 8; ++i)
            cp16(smem_u32(&xsm[b][xdo[i]]), xsrc[i] + ko);
        #pragma unroll
        for (int i = 0; i < 4; ++i)
            cp16(smem_u32(&wsm[b][wdo[i]]), wsrc[i] + ko);
        cp_commit();
    };

    // ---- compute-side constants ----
    const int cl  = tig >> 1;
    const int sub = (tig & 1) * 8;
    const int cA0 = (((4 * warp + cl)     ^ gid) << 4) + sub;
    const int cA1 = (((4 * warp + cl + 2) ^ gid) << 4) + sub;
    const int cB  = (((2 * warp + cl)     ^ gid) << 4) + sub;

    float acc[4][4][4];
    #pragma unroll
    for (int m = 0; m < 4; ++m)
        #pragma unroll
        for (int j = 0; j < 4; ++j)
            #pragma unroll
            for (int q = 0; q < 4; ++q) acc[m][j][q] = 0.0f;

    stage(0, 0);
    stage(1, 1);

    for (int s = 0; s < NST; ++s) {
        if (s + 2 < NST) { stage(s + 2, (s + 2) % 3); cp_wait<2>(); }
        else if (s + 1 < NST) { cp_wait<1>(); }
        else { cp_wait<0>(); }
        __syncwarp();                 // warp-scope visibility; no block barrier

        const char* xb = xsm[s % 3];
        const char* wb = wsm[s % 3];

        uint2 bh[4], bl[4];
        #pragma unroll
        for (int j = 0; j < 4; ++j) {
            const int e = 8 * j + gid;
            bh[j] = *reinterpret_cast<const uint2*>(wb + e * WROW + cB);
            bl[j] = *reinterpret_cast<const uint2*>(wb + WPLANE + e * WROW + cB);
        }

        #pragma unroll
        for (int m = 0; m < 4; ++m) {
            const int r0 = m * 16 + gid, r1 = r0 + 8;
            float2 f00 = *reinterpret_cast<const float2*>(xb + r0 * XROW + cA0);
            float2 f10 = *reinterpret_cast<const float2*>(xb + r1 * XROW + cA0);
            float2 f01 = *reinterpret_cast<const float2*>(xb + r0 * XROW + cA1);
            float2 f11 = *reinterpret_cast<const float2*>(xb + r1 * XROW + cA1);
            unsigned ah[4], al[4];
            cvt_hl(f00, ah[0], al[0]);
            cvt_hl(f10, ah[1], al[1]);
            cvt_hl(f01, ah[2], al[2]);
            cvt_hl(f11, ah[3], al[3]);

            #pragma unroll
            for (int j = 0; j < 4; ++j) {
                hmma(acc[m][j], ah, bh[j].x, bh[j].y);
                hmma(acc[m][j], al, bh[j].x, bh[j].y);
                hmma(acc[m][j], ah, bl[j].x, bl[j].y);
            }
        }
        __syncwarp();                 // buffer s reads done before lanes re-stage it
    }

    // ---- cross-warp K reduction ----
    float (*part)[BM][E_EXP] = reinterpret_cast<float (*)[BM][E_EXP]>(&xsm[0][0]); // 96KB
    __syncthreads();                  // all warps done with smem before aliasing
    #pragma unroll
    for (int m = 0; m < 4; ++m)
        #pragma unroll
        for (int j = 0; j < 4; ++j) {
            const int e = 8 * j + 2 * tig;
            part[warp][m * 16 + gid][e]         = acc[m][j][0];
            part[warp][m * 16 + gid][e + 1]     = acc[m][j][1];
            part[warp][m * 16 + gid + 8][e]     = acc[m][j][2];
            part[warp][m * 16 + gid + 8][e + 1] = acc[m][j][3];
        }
    __syncthreads();

    if (tid < BM) {
        const int t = tid;
        float bv0 = -1e30f, bv1 = -1e30f, bv2 = -1e30f, bv3 = -1e30f;
        int   bi0 = 0, bi1 = 0, bi2 = 0, bi3 = 0;
        #pragma unroll
        for (int e = 0; e < E_EXP; ++e) {
            float lv = bias[e];
            #pragma unroll
            for (int wsum = 0; wsum < NWARP; ++wsum) lv += part[wsum][t][e];
            if (lv > bv3) {
                if (lv > bv0) {
                    bv3 = bv2; bi3 = bi2; bv2 = bv1; bi2 = bi1; bv1 = bv0; bi1 = bi0;
                    bv0 = lv;  bi0 = e;
                } else if (lv > bv1) {
                    bv3 = bv2; bi3 = bi2; bv2 = bv1; bi2 = bi1;
                    bv1 = lv;  bi1 = e;
                } else if (lv > bv2) {
                    bv3 = bv2; bi3 = bi2;
                    bv2 = lv;  bi2 = e;
                } else {
                    bv3 = lv;  bi3 = e;
                }
            }
        }
        float e0 = 1.0f;
        float e1 = expf(bv1 - bv0);
        float e2 = expf(bv2 - bv0);
        float e3 = expf(bv3 - bv0);
        float inv = 1.0f / (e0 + e1 + e2 + e3);

        const int gt = t0 + t;
        float* oi = out + (size_t)gt * TOPK;
        float* ow = out + (size_t)T_TOKENS * TOPK + (size_t)gt * TOPK;
        oi[0] = (float)bi0; oi[1] = (float)bi1; oi[2] = (float)bi2; oi[3] = (float)bi3;
        ow[0] = e0 * inv;   ow[1] = e1 * inv;   ow[2] = e2 * inv;   ow[3] = e3 * inv;
    }
}

extern "C" void kernel_launch(void* const* d_in, const int* in_sizes, int n_in,
                              void* d_out, int out_size)
{
    const float* x    = (const float*)d_in[0];  // [4,4096,2880] f32
    const float* w    = (const float*)d_in[1];  // [32,2880] f32
    const float* bias = (const float*)d_in[2];  // [32] f32
    float* out = (float*)d_out;

    convert_w<<<(E_EXP * H_DIM + 255) / 256, 256>>>(w);
    gate_mma<<<T_TOKENS / BM, NTHREADS>>>(x, bias, out);   // 256 CTAs x 12 warps (K-split 12)
}

// round 14
// speedup vs baseline: 1.3672x; 1.3672x over previous
#include <cuda_runtime.h>
#include <cuda_bf16.h>

#define T_TOKENS 16384
#define H_DIM    2880
#define E_EXP    32
#define TOPK     4
#define BM       64
#define KPW      (H_DIM / 4)        // 720 per warp
#define NST      (KPW / 16)         // 45 stages of k16 per warp
#define NTHREADS 128
#define NBUF     4

// W bf16 hi/lo planes, k-INTERLEAVED within each 16-group so one LDS.64 = (b0,b1) frag:
// pos(k) within 16: {0,1,8,9, 2,3,10,11, 4,5,12,13, 6,7,14,15}
__device__ __nv_bfloat16 g_wh[E_EXP * H_DIM];
__device__ __nv_bfloat16 g_wl[E_EXP * H_DIM];

__global__ __launch_bounds__(256)
void convert_w(const float* __restrict__ w)
{
    int i = blockIdx.x * 256 + threadIdx.x;
    if (i < E_EXP * H_DIM) {
        int k   = i % H_DIM;
        int kb  = k & ~15;
        int k16 = k & 15;
        int pos = ((k16 & 7) >> 1) * 4 + ((k16 >> 3) << 1) + (k16 & 1);
        int j   = i - k + kb + pos;
        float v = w[i];
        __nv_bfloat16 h = __float2bfloat16_rn(v);
        g_wh[j] = h;
        g_wl[j] = __float2bfloat16_rn(v - __bfloat162float(h));
    }
}

__device__ __forceinline__ unsigned smem_u32(const void* p) {
    return (unsigned)__cvta_generic_to_shared(p);
}
__device__ __forceinline__ void cp16(unsigned dst, const void* src) {
    asm volatile("cp.async.cg.shared.global [%0], [%1], 16;" :: "r"(dst), "l"(src));
}
__device__ __forceinline__ void cp_commit() {
    asm volatile("cp.async.commit_group;");
}
template <int N>
__device__ __forceinline__ void cp_wait() {
    asm volatile("cp.async.wait_group %0;" :: "n"(N));
}
__device__ __forceinline__ void cvt_hl(float2 f, unsigned& h, unsigned& l)
{
    asm("cvt.rn.bf16x2.f32 %0, %1, %2;" : "=r"(h) : "f"(f.y), "f"(f.x));
    float h0 = __uint_as_float(h << 16);
    float h1 = __uint_as_float(h & 0xffff0000u);
    asm("cvt.rn.bf16x2.f32 %0, %1, %2;" : "=r"(l) : "f"(f.y - h1), "f"(f.x - h0));
}
__device__ __forceinline__ void hmma(float* d, const unsigned* a, unsigned b0, unsigned b1)
{
    asm volatile(
        "mma.sync.aligned.m16n8k16.row.col.f32.bf16.bf16.f32 "
        "{%0,%1,%2,%3}, {%4,%5,%6,%7}, {%8,%9}, {%0,%1,%2,%3};"
        : "+f"(d[0]), "+f"(d[1]), "+f"(d[2]), "+f"(d[3])
        : "r"(a[0]), "r"(a[1]), "r"(a[2]), "r"(a[3]), "r"(b0), "r"(b1));
}

__global__ __launch_bounds__(NTHREADS, 2)
void gate_mma(const float* __restrict__ x,
              const float* __restrict__ bias,
              float* __restrict__ out)
{
    // Shared buffers with warp-private COLUMN regions (warp w owns x-chunks 4w..4w+3,
    // w-chunks 2w..2w+1, pre-XOR). Swizzles bijective per row -> regions disjoint.
    __shared__ __align__(16) char xsm[NBUF][BM * 256];        // 64 KB  (x: [tok][16 chunks])
    __shared__ __align__(16) char wsm[NBUF][2 * E_EXP * 128]; // 32 KB  (w: [pl][e][8 chunks])

    const int tid  = threadIdx.x;
    const int warp = tid >> 5;
    const int lane = tid & 31;
    const int gid  = lane >> 2;       // 0..7
    const int tig  = lane & 3;        // 0..3
    const int t0   = blockIdx.x * BM;
    const int kb   = warp * KPW;      // this warp's K base

    // ---- warp-private staging maps ----
    // x: 256 chunks/stage (64 tok x 4 chunks): id = lane + 32*i (i<8): tok=id>>2, kc=id&3
    const float* xsrc[8];
    int xdo[8];
    #pragma unroll
    for (int i = 0; i < 8; ++i) {
        int id  = lane + 32 * i;
        int tok = id >> 2, kc = id & 3;
        xsrc[i] = x + (size_t)(t0 + tok) * H_DIM + kb + kc * 4;
        xdo[i]  = tok * 256 + (((4 * warp + kc) ^ (tok & 7)) << 4);
    }
    // w: 128 chunks/stage (2 pl x 32 e x 2 halves): id = lane + 32*i (i<4)
    const __nv_bfloat16* wsrc[4];
    int wdo[4];
    #pragma unroll
    for (int i = 0; i < 4; ++i) {
        int id = lane + 32 * i;
        int pl = id >> 6, e = (id >> 1) & 31, h = id & 1;
        wsrc[i] = (pl ? g_wl : g_wh) + (size_t)e * H_DIM + kb + h * 8;
        wdo[i]  = pl * 4096 + e * 128 + (((2 * warp + h) ^ (e & 7)) << 4);
    }

    auto stage = [&](int s, int b) {
        const size_t ko = (size_t)s * 16;
        #pragma unroll
        for (int i = 0; i < 8; ++i)
            cp16(smem_u32(&xsm[b][xdo[i]]), xsrc[i] + ko);
        #pragma unroll
        for (int i = 0; i < 4; ++i)
            cp16(smem_u32(&wsm[b][wdo[i]]), wsrc[i] + ko);
        cp_commit();
    };

    // ---- compute-side constants ----
    const int cl  = tig >> 1;
    const int sub = (tig & 1) * 8;
    const int cA0 = (((4 * warp + cl)     ^ gid) << 4) + sub;
    const int cA1 = (((4 * warp + cl + 2) ^ gid) << 4) + sub;
    const int cB  = (((2 * warp + cl)     ^ gid) << 4) + sub;

    // acc[m][j]: token tile m (rows m*16+gid, +8), expert 8j+gid
    float acc[4][4][4];
    #pragma unroll
    for (int m = 0; m < 4; ++m)
        #pragma unroll
        for (int j = 0; j < 4; ++j)
            #pragma unroll
            for (int q = 0; q < 4; ++q) acc[m][j][q] = 0.0f;

    // prologue: 3 stages in flight (depth-3 lookahead)
    stage(0, 0);
    stage(1, 1);
    stage(2, 2);

    for (int s = 0; s < NST; ++s) {
        if (s + 3 < NST)      { stage(s + 3, (s + 3) % NBUF); cp_wait<3>(); }
        else if (s + 2 < NST) { cp_wait<2>(); }
        else if (s + 1 < NST) { cp_wait<1>(); }
        else                  { cp_wait<0>(); }
        __syncwarp();                 // warp-scope visibility; no block barrier

        const char* xb = xsm[s % NBUF];
        const char* wb = wsm[s % NBUF];

        // B fragments for this warp's k16 (hoisted: shared by all 4 token tiles)
        uint2 bh[4], bl[4];
        #pragma unroll
        for (int j = 0; j < 4; ++j) {
            const int e = 8 * j + gid;
            bh[j] = *reinterpret_cast<const uint2*>(wb + e * 128 + cB);
            bl[j] = *reinterpret_cast<const uint2*>(wb + 4096 + e * 128 + cB);
        }

        #pragma unroll
        for (int m = 0; m < 4; ++m) {
            const int r0 = m * 16 + gid, r1 = r0 + 8;
            float2 f00 = *reinterpret_cast<const float2*>(xb + r0 * 256 + cA0);
            float2 f10 = *reinterpret_cast<const float2*>(xb + r1 * 256 + cA0);
            float2 f01 = *reinterpret_cast<const float2*>(xb + r0 * 256 + cA1);
            float2 f11 = *reinterpret_cast<const float2*>(xb + r1 * 256 + cA1);
            unsigned ah[4], al[4];
            cvt_hl(f00, ah[0], al[0]);
            cvt_hl(f10, ah[1], al[1]);
            cvt_hl(f01, ah[2], al[2]);
            cvt_hl(f11, ah[3], al[3]);

            #pragma unroll
            for (int j = 0; j < 4; ++j) {
                hmma(acc[m][j], ah, bh[j].x, bh[j].y);
                hmma(acc[m][j], al, bh[j].x, bh[j].y);
                hmma(acc[m][j], ah, bl[j].x, bl[j].y);
            }
        }
        __syncwarp();                 // buffer s reads done before lanes re-stage it
    }

    // ---- cross-warp K reduction ----
    float (*part)[BM][E_EXP] = reinterpret_cast<float (*)[BM][E_EXP]>(&xsm[0][0]); // 32KB
    __syncthreads();                  // all warps done with smem before aliasing
    #pragma unroll
    for (int m = 0; m < 4; ++m)
        #pragma unroll
        for (int j = 0; j < 4; ++j) {
            const int e = 8 * j + 2 * tig;
            part[warp][m * 16 + gid][e]         = acc[m][j][0];
            part[warp][m * 16 + gid][e + 1]     = acc[m][j][1];
            part[warp][m * 16 + gid + 8][e]     = acc[m][j][2];
            part[warp][m * 16 + gid + 8][e + 1] = acc[m][j][3];
        }
    __syncthreads();

    if (tid < BM) {
        const int t = tid;
        float bv0 = -1e30f, bv1 = -1e30f, bv2 = -1e30f, bv3 = -1e30f;
        int   bi0 = 0, bi1 = 0, bi2 = 0, bi3 = 0;
        #pragma unroll
        for (int e = 0; e < E_EXP; ++e) {
            float lv = part[0][t][e] + part[1][t][e] + part[2][t][e] + part[3][t][e]
                     + bias[e];
            if (lv > bv3) {
                if (lv > bv0) {
                    bv3 = bv2; bi3 = bi2; bv2 = bv1; bi2 = bi1; bv1 = bv0; bi1 = bi0;
                    bv0 = lv;  bi0 = e;
                } else if (lv > bv1) {
                    bv3 = bv2; bi3 = bi2; bv2 = bv1; bi2 = bi1;
                    bv1 = lv;  bi1 = e;
                } else if (lv > bv2) {
                    bv3 = bv2; bi3 = bi2;
                    bv2 = lv;  bi2 = e;
                } else {
                    bv3 = lv;  bi3 = e;
                }
            }
        }
        float e0 = 1.0f;
        float e1 = expf(bv1 - bv0);
        float e2 = expf(bv2 - bv0);
        float e3 = expf(bv3 - bv0);
        float inv = 1.0f / (e0 + e1 + e2 + e3);

        const int gt = t0 + t;
        float* oi = out + (size_t)gt * TOPK;
        float* ow = out + (size_t)T_TOKENS * TOPK + (size_t)gt * TOPK;
        oi[0] = (float)bi0; oi[1] = (float)bi1; oi[2] = (float)bi2; oi[3] = (float)bi3;
        ow[0] = e0 * inv;   ow[1] = e1 * inv;   ow[2] = e2 * inv;   ow[3] = e3 * inv;
    }
}

extern "C" void kernel_launch(void* const* d_in, const int* in_sizes, int n_in,
                              void* d_out, int out_size)
{
    const float* x    = (const float*)d_in[0];  // [4,4096,2880] f32
    const float* w    = (const float*)d_in[1];  // [32,2880] f32
    const float* bias = (const float*)d_in[2];  // [32] f32
    float* out = (float*)d_out;

    convert_w<<<(E_EXP * H_DIM + 255) / 256, 256>>>(w);
    gate_mma<<<T_TOKENS / BM, NTHREADS>>>(x, bias, out);   // 256 CTAs x 4 warps (K-split, depth-3)
}